// round 11
// baseline (speedup 1.0000x reference)
#include <cuda_runtime.h>

#define CH   4194304      // 256*256*64 = 2^22
#define SXY  16384        // 256*64 (x stride)
#define EPSF 1e-10f

__device__ double g_acc[3];        // [0]=loss_b, [1]=parallel, [2]=div
__device__ unsigned int g_done;    // zero-initialized

__device__ __forceinline__ float cell_div(
    float bx000, float bx100, float bx010, float bx110,
    float bx001, float bx101, float bx011, float bx111,
    float by000, float by100, float by010, float by110,
    float by001, float by101, float by011, float by111,
    float bz000, float bz100, float bz010, float bz110,
    float bz001, float bz101, float bz011, float bz111,
    float z000,  float z100,  float z010,  float z110,
    float z001,  float z101,  float z011,  float z111)
{
    const float DXf = 0.1f, DYf = 0.1f, SIXTH = 1.f / 6.f;
    float dk00 = z001 - z000;
    float dk10 = z101 - z100;
    float dk01 = z011 - z010;
    float dk11 = z111 - z110;

    float px = 0.125f * ((bx100 + bx110 + bx101 + bx111) * (dk10 + dk11)
                       - (bx000 + bx010 + bx001 + bx011) * (dk00 + dk01))
             + SIXTH  * ((bx001 + bx101 + bx111) * (z001 - z101)
                       + (bx011 + bx111 + bx101) * (z011 - z111)
                       - (bx000 + bx100 + bx110) * (z000 - z100)
                       - (bx010 + bx110 + bx100) * (z010 - z110));

    float py = 0.125f * ((by010 + by110 + by011 + by111) * (dk01 + dk11)
                       - (by000 + by100 + by001 + by101) * (dk00 + dk10))
             + SIXTH  * ((by101 + by111 + by011) * (z101 - z111)
                       + (by001 + by011 + by111) * (z001 - z011)
                       - (by100 + by110 + by010) * (z100 - z110)
                       - (by000 + by010 + by110) * (z000 - z010));

    float szHi = bz001 + bz011 + bz101 + bz111;
    float szLo = bz000 + bz010 + bz100 + bz110;
    float pz = 0.25f * (szHi - szLo);

    float num = DYf * px + DXf * py + (DXf * DYf) * pz;

    float bxc = 0.125f * (bx000 + bx100 + bx010 + bx110 + bx001 + bx101 + bx011 + bx111);
    float byc = 0.125f * (by000 + by100 + by010 + by110 + by001 + by101 + by011 + by111);
    float bzc = 0.125f * (szHi + szLo);
    float den = bxc*bxc + byc*byc + bzc*bzc + EPSF;
    return __fdividef(num * num, den);
}

// One fused kernel, 32768 blocks of 128 threads.
// Even blockIdx -> pointwise path (block index bid>>1 of 16384).
// Odd  blockIdx -> divergence path (block index bid>>1 of 16384).
// Interleaving by parity puts ~50/50 pw/div blocks in every wave so each SM
// overlaps pw's DRAM latency with div's issue/FMA stream.
__global__ __launch_bounds__(128, 6)
void k_fused(const float* __restrict__ O, const float* __restrict__ T,
             float* __restrict__ out, int nblocks) {
    const int tx  = threadIdx.x;          // 0..15
    const int ty  = threadIdx.y;          // 0..7
    const int lin = ty * 16 + tx;         // 0..127
    const int bid = blockIdx.x;
    const int sub = bid >> 1;             // 0..16383 within each path

    const float4* O4 = (const float4*)O;
    const float4* T4 = (const float4*)T;
    const unsigned FULL = 0xffffffffu;

    __shared__ double s0[4], s1[4], s2[4];

    double r0 = 0.0, r1 = 0.0, r2 = 0.0;  // this block's partials

    if ((bid & 1) == 0) {
        // ======================= pointwise path =======================
        const int off = (sub * 128 + lin) << 2;   // element offset in [0, 2*CH)
        const int b   = off >> 22;
        const int sp  = off & (CH - 1);
        const int ob  = b * 3 * CH;
        const int tb  = b * 4 * CH;

        float4 pbx = O4[(ob          + sp) >> 2];
        float4 pby = O4[(ob + CH     + sp) >> 2];
        float4 pbz = O4[(ob + 2*CH   + sp) >> 2];
        float4 qbx = T4[(tb          + sp) >> 2];
        float4 qby = T4[(tb + CH     + sp) >> 2];
        float4 qbz = T4[(tb + 2*CH   + sp) >> 2];

        float accb = 0.f, accp = 0.f;

#define PW(px, py, pz, qx, qy, qz) {                                   \
    float qx2 = (qx)*(qx), qy2 = (qy)*(qy), qz2 = (qz)*(qz);           \
    float v1 = (px)*(px) + (py)*(py) - qx2 - qy2;                      \
    accb += __fdividef(v1 * v1, qx2 + qy2 + EPSF);                     \
    float dz = (pz) - (qz); float dz2 = dz * dz;                       \
    accb += __fdividef(dz2 * dz2, qz2 + EPSF);                         \
    float cr = (px)*(qy) - (py)*(qx);                                  \
    accp += __fdividef(cr * cr, qx2 + qy2 + qz2 + EPSF); }

        PW(pbx.x, pby.x, pbz.x, qbx.x, qby.x, qbz.x);
        PW(pbx.y, pby.y, pbz.y, qbx.y, qby.y, qbz.y);
        PW(pbx.z, pby.z, pbz.z, qbx.z, qby.z, qbz.z);
        PW(pbx.w, pby.w, pbz.w, qbx.w, qby.w, qbz.w);
#undef PW

        r0 = (double)accb;
        r1 = (double)accp;
    } else {
        // ======================= divergence path =======================
        const int y  = ((sub & 31) << 3) + ty;
        const int x  = (sub >> 5) & 255;
        const int b  = sub >> 13;
        const int sp = (x * 256 + y) * 64 + (tx << 2);
        const int ob = b * 3 * CH;
        const int cz = b * 4 * CH + 3 * CH;
        const bool live = (x < 255) && (y < 255);

        float4 ax00, ax10, ax01, ax11;
        float4 ay00, ay10, ay01, ay11;
        float4 az00, az10, az01, az11;
        float4 aw00, aw10, aw01, aw11;
        if (live) {
            const int s10 = sp + SXY;
            const int s01 = sp + 64;
            const int s11 = s10 + 64;
            ax00 = O4[(ob          + sp ) >> 2];
            ax10 = O4[(ob          + s10) >> 2];
            ax01 = O4[(ob          + s01) >> 2];
            ax11 = O4[(ob          + s11) >> 2];
            ay00 = O4[(ob + CH     + sp ) >> 2];
            ay10 = O4[(ob + CH     + s10) >> 2];
            ay01 = O4[(ob + CH     + s01) >> 2];
            ay11 = O4[(ob + CH     + s11) >> 2];
            az00 = O4[(ob + 2*CH   + sp ) >> 2];
            az10 = O4[(ob + 2*CH   + s10) >> 2];
            az01 = O4[(ob + 2*CH   + s01) >> 2];
            az11 = O4[(ob + 2*CH   + s11) >> 2];
            aw00 = T4[(cz          + sp ) >> 2];
            aw10 = T4[(cz          + s10) >> 2];
            aw01 = T4[(cz          + s01) >> 2];
            aw11 = T4[(cz          + s11) >> 2];
        } else {
            ax00 = ax10 = ax01 = ax11 = ay00 = ay10 = ay01 = ay11 =
            az00 = az10 = az01 = az11 = aw00 = aw10 = aw01 = aw11 =
                make_float4(0.f, 0.f, 0.f, 0.f);
        }

        float tx00 = __shfl_down_sync(FULL, ax00.x, 1);
        float tx10 = __shfl_down_sync(FULL, ax10.x, 1);
        float tx01 = __shfl_down_sync(FULL, ax01.x, 1);
        float tx11 = __shfl_down_sync(FULL, ax11.x, 1);
        float ty00 = __shfl_down_sync(FULL, ay00.x, 1);
        float ty10 = __shfl_down_sync(FULL, ay10.x, 1);
        float ty01 = __shfl_down_sync(FULL, ay01.x, 1);
        float ty11 = __shfl_down_sync(FULL, ay11.x, 1);
        float tz00 = __shfl_down_sync(FULL, az00.x, 1);
        float tz10 = __shfl_down_sync(FULL, az10.x, 1);
        float tz01 = __shfl_down_sync(FULL, az01.x, 1);
        float tz11 = __shfl_down_sync(FULL, az11.x, 1);
        float tw00 = __shfl_down_sync(FULL, aw00.x, 1);
        float tw10 = __shfl_down_sync(FULL, aw10.x, 1);
        float tw01 = __shfl_down_sync(FULL, aw01.x, 1);
        float tw11 = __shfl_down_sync(FULL, aw11.x, 1);

        float accd = 0.f;
        if (live) {
            accd += cell_div(ax00.x, ax10.x, ax01.x, ax11.x,  ax00.y, ax10.y, ax01.y, ax11.y,
                             ay00.x, ay10.x, ay01.x, ay11.x,  ay00.y, ay10.y, ay01.y, ay11.y,
                             az00.x, az10.x, az01.x, az11.x,  az00.y, az10.y, az01.y, az11.y,
                             aw00.x, aw10.x, aw01.x, aw11.x,  aw00.y, aw10.y, aw01.y, aw11.y);
            accd += cell_div(ax00.y, ax10.y, ax01.y, ax11.y,  ax00.z, ax10.z, ax01.z, ax11.z,
                             ay00.y, ay10.y, ay01.y, ay11.y,  ay00.z, ay10.z, ay01.z, ay11.z,
                             az00.y, az10.y, az01.y, az11.y,  az00.z, az10.z, az01.z, az11.z,
                             aw00.y, aw10.y, aw01.y, aw11.y,  aw00.z, aw10.z, aw01.z, aw11.z);
            accd += cell_div(ax00.z, ax10.z, ax01.z, ax11.z,  ax00.w, ax10.w, ax01.w, ax11.w,
                             ay00.z, ay10.z, ay01.z, ay11.z,  ay00.w, ay10.w, ay01.w, ay11.w,
                             az00.z, az10.z, az01.z, az11.z,  az00.w, az10.w, az01.w, az11.w,
                             aw00.z, aw10.z, aw01.z, aw11.z,  aw00.w, aw10.w, aw01.w, aw11.w);
            if (tx < 15) {
                accd += cell_div(ax00.w, ax10.w, ax01.w, ax11.w,  tx00, tx10, tx01, tx11,
                                 ay00.w, ay10.w, ay01.w, ay11.w,  ty00, ty10, ty01, ty11,
                                 az00.w, az10.w, az01.w, az11.w,  tz00, tz10, tz01, tz11,
                                 aw00.w, aw10.w, aw01.w, aw11.w,  tw00, tw10, tw01, tw11);
            }
        }
        r2 = (double)accd;
    }

    // ---- unified block reduction: warp shfl (double) -> smem -> atomics ----
#pragma unroll
    for (int o = 16; o > 0; o >>= 1) {
        r0 += __shfl_xor_sync(FULL, r0, o);
        r1 += __shfl_xor_sync(FULL, r1, o);
        r2 += __shfl_xor_sync(FULL, r2, o);
    }
    if ((lin & 31) == 0) {
        int w = lin >> 5;
        s0[w] = r0; s1[w] = r1; s2[w] = r2;
    }
    __syncthreads();
    if (lin == 0) {
        double a = s0[0] + s0[1] + s0[2] + s0[3];
        double c = s1[0] + s1[1] + s1[2] + s1[3];
        double d = s2[0] + s2[1] + s2[2] + s2[3];
        if ((bid & 1) == 0) {
            atomicAdd(&g_acc[0], a);
            atomicAdd(&g_acc[1], c);
        } else {
            atomicAdd(&g_acc[2], d);
        }
        __threadfence();
        unsigned int prev = atomicAdd(&g_done, 1u);
        if (prev == (unsigned)(nblocks - 1)) {
            __threadfence();
            const double N1 = 8388608.0;   // 2*256*256*64
            const double N2 = 8193150.0;   // 2*255*255*63
            double lb = g_acc[0] / N1;
            double lp = g_acc[1] / N1;
            double ld = g_acc[2] / N2;
            double dx2 = 0.1 * 0.1;
            out[0] = (float)(1000.0 * lb + 1000.0 * lp);
            out[1] = (float)(100.0 * ld / dx2 / dx2);
            g_acc[0] = 0.0; g_acc[1] = 0.0; g_acc[2] = 0.0;
            g_done = 0u;
            __threadfence();
        }
    }
}

extern "C" void kernel_launch(void* const* d_in, const int* in_sizes, int n_in,
                              void* d_out, int out_size) {
    const float* O = (const float*)d_in[0];   // outputs (2,3,256,256,64)
    const float* T = (const float*)d_in[1];   // targets (2,4,256,256,64)
    k_fused<<<32768, dim3(16, 8)>>>(O, T, (float*)d_out, 32768);
}

// round 14
// speedup vs baseline: 1.4258x; 1.4258x over previous
#include <cuda_runtime.h>

#define CH   4194304      // 256*256*64 = 2^22
#define SXY  16384        // 256*64 (x stride)
#define EPSF 1e-10f

__device__ double g_acc[3];        // [0]=loss_b, [1]=parallel, [2]=div
__device__ unsigned int g_done;    // zero-initialized

// ============================================================================
// Kernel A: pointwise losses. 8 floats/thread/channel -> 12 LDG.128 in flight.
// ============================================================================
__global__ __launch_bounds__(256)
void k_pw(const float* __restrict__ O, const float* __restrict__ T) {
    const int t   = blockIdx.x * 256 + threadIdx.x;   // 0 .. 2*CH/8 - 1
    const int off = t << 3;                           // element offset, 8 per thread
    const int b   = off >> 22;                        // batch
    const int sp  = off & (CH - 1);                   // 8-aligned, same channel
    const int ob  = b * 3 * CH;
    const int tb  = b * 4 * CH;
    const float4* O4 = (const float4*)O;
    const float4* T4 = (const float4*)T;

    const int i0 = (ob          + sp) >> 2;
    const int i1 = (ob + CH     + sp) >> 2;
    const int i2 = (ob + 2*CH   + sp) >> 2;
    const int j0 = (tb          + sp) >> 2;
    const int j1 = (tb + CH     + sp) >> 2;
    const int j2 = (tb + 2*CH   + sp) >> 2;

    float4 pbx0 = O4[i0],     pbx1 = O4[i0 + 1];
    float4 pby0 = O4[i1],     pby1 = O4[i1 + 1];
    float4 pbz0 = O4[i2],     pbz1 = O4[i2 + 1];
    float4 qbx0 = T4[j0],     qbx1 = T4[j0 + 1];
    float4 qby0 = T4[j1],     qby1 = T4[j1 + 1];
    float4 qbz0 = T4[j2],     qbz1 = T4[j2 + 1];

    float accb = 0.f, accp = 0.f;

#define PW(px, py, pz, qx, qy, qz) {                                   \
    float qx2 = (qx)*(qx), qy2 = (qy)*(qy), qz2 = (qz)*(qz);           \
    float v1 = (px)*(px) + (py)*(py) - qx2 - qy2;                      \
    accb += __fdividef(v1 * v1, qx2 + qy2 + EPSF);                     \
    float dz = (pz) - (qz); float dz2 = dz * dz;                       \
    accb += __fdividef(dz2 * dz2, qz2 + EPSF);                         \
    float cr = (px)*(qy) - (py)*(qx);                                  \
    accp += __fdividef(cr * cr, qx2 + qy2 + qz2 + EPSF); }

    PW(pbx0.x, pby0.x, pbz0.x, qbx0.x, qby0.x, qbz0.x);
    PW(pbx0.y, pby0.y, pbz0.y, qbx0.y, qby0.y, qbz0.y);
    PW(pbx0.z, pby0.z, pbz0.z, qbx0.z, qby0.z, qbz0.z);
    PW(pbx0.w, pby0.w, pbz0.w, qbx0.w, qby0.w, qbz0.w);
    PW(pbx1.x, pby1.x, pbz1.x, qbx1.x, qby1.x, qbz1.x);
    PW(pbx1.y, pby1.y, pbz1.y, qbx1.y, qby1.y, qbz1.y);
    PW(pbx1.z, pby1.z, pbz1.z, qbx1.z, qby1.z, qbz1.z);
    PW(pbx1.w, pby1.w, pbz1.w, qbx1.w, qby1.w, qbz1.w);
#undef PW

    double db = (double)accb, dp = (double)accp;
#pragma unroll
    for (int o = 16; o > 0; o >>= 1) {
        db += __shfl_xor_sync(0xffffffffu, db, o);
        dp += __shfl_xor_sync(0xffffffffu, dp, o);
    }
    __shared__ double sb[8], sp_[8];
    const int lin = threadIdx.x;
    if ((lin & 31) == 0) { sb[lin >> 5] = db; sp_[lin >> 5] = dp; }
    __syncthreads();
    if (lin == 0) {
        double a = 0.0, c = 0.0;
#pragma unroll
        for (int w = 0; w < 8; w++) { a += sb[w]; c += sp_[w]; }
        atomicAdd(&g_acc[0], a);
        atomicAdd(&g_acc[1], c);
    }
}

// ============================================================================
// Kernel B: divergence loss, field-phased (z -> bx -> by -> bz) to shrink
// peak register state; per-cell num/den accumulators carried across phases.
// ============================================================================
// tx 0..15 -> k0=4*tx, ty 0..7 -> y in group. Grid 16384 = b(2)*x(256)*yg(32).
__global__ __launch_bounds__(128, 7)
void k_div(const float* __restrict__ O, const float* __restrict__ T,
           float* __restrict__ out, int nblocks) {
    const int tx = threadIdx.x;
    const int ty = threadIdx.y;
    const int bid = blockIdx.x;
    const int y  = ((bid & 31) << 3) + ty;
    const int x  = (bid >> 5) & 255;
    const int b  = bid >> 13;
    const int sp = (x * 256 + y) * 64 + (tx << 2);
    const int s10 = sp + SXY;
    const int s01 = sp + 64;
    const int s11 = s10 + 64;
    const int ob = b * 3 * CH;
    const int cz = b * 4 * CH + 3 * CH;

    const float4* O4 = (const float4*)O;
    const float4* T4 = (const float4*)T;
    const unsigned FULL = 0xffffffffu;
    const bool live = (x < 255) && (y < 255);
    const float DXf = 0.1f, DYf = 0.1f, SIXTH = 1.f / 6.f;

    float num[4] = {0.f, 0.f, 0.f, 0.f};
    float den[4] = {0.f, 0.f, 0.f, 0.f};

    // ---------- phase Z: targets channel 3 (persistent all phases) ----------
    float4 w00, w10, w01, w11;
    if (live) {
        w00 = T4[(cz + sp ) >> 2];
        w10 = T4[(cz + s10) >> 2];
        w01 = T4[(cz + s01) >> 2];
        w11 = T4[(cz + s11) >> 2];
    } else {
        w00 = w10 = w01 = w11 = make_float4(0.f, 0.f, 0.f, 0.f);
    }
    float Z00[5] = {w00.x, w00.y, w00.z, w00.w, __shfl_down_sync(FULL, w00.x, 1)};
    float Z10[5] = {w10.x, w10.y, w10.z, w10.w, __shfl_down_sync(FULL, w10.x, 1)};
    float Z01[5] = {w01.x, w01.y, w01.z, w01.w, __shfl_down_sync(FULL, w01.x, 1)};
    float Z11[5] = {w11.x, w11.y, w11.z, w11.w, __shfl_down_sync(FULL, w11.x, 1)};

    // ---------- phase BX ----------
    {
        float4 f00, f10, f01, f11;
        if (live) {
            f00 = O4[(ob + sp ) >> 2];
            f10 = O4[(ob + s10) >> 2];
            f01 = O4[(ob + s01) >> 2];
            f11 = O4[(ob + s11) >> 2];
        } else {
            f00 = f10 = f01 = f11 = make_float4(0.f, 0.f, 0.f, 0.f);
        }
        float X00[5] = {f00.x, f00.y, f00.z, f00.w, __shfl_down_sync(FULL, f00.x, 1)};
        float X10[5] = {f10.x, f10.y, f10.z, f10.w, __shfl_down_sync(FULL, f10.x, 1)};
        float X01[5] = {f01.x, f01.y, f01.z, f01.w, __shfl_down_sync(FULL, f01.x, 1)};
        float X11[5] = {f11.x, f11.y, f11.z, f11.w, __shfl_down_sync(FULL, f11.x, 1)};
        if (live) {
#pragma unroll
            for (int j = 0; j < 4; j++) {
                float dk00 = Z00[j+1] - Z00[j];
                float dk10 = Z10[j+1] - Z10[j];
                float dk01 = Z01[j+1] - Z01[j];
                float dk11 = Z11[j+1] - Z11[j];
                float px = 0.125f * ((X10[j] + X11[j] + X10[j+1] + X11[j+1]) * (dk10 + dk11)
                                   - (X00[j] + X01[j] + X00[j+1] + X01[j+1]) * (dk00 + dk01))
                         + SIXTH  * ((X00[j+1] + X10[j+1] + X11[j+1]) * (Z00[j+1] - Z10[j+1])
                                   + (X01[j+1] + X11[j+1] + X10[j+1]) * (Z01[j+1] - Z11[j+1])
                                   - (X00[j] + X10[j] + X11[j]) * (Z00[j] - Z10[j])
                                   - (X01[j] + X11[j] + X10[j]) * (Z01[j] - Z11[j]));
                float bxc = 0.125f * (X00[j] + X10[j] + X01[j] + X11[j]
                                    + X00[j+1] + X10[j+1] + X01[j+1] + X11[j+1]);
                num[j] += DYf * px;
                den[j] += bxc * bxc;
            }
        }
    }

    // ---------- phase BY ----------
    {
        float4 f00, f10, f01, f11;
        if (live) {
            f00 = O4[(ob + CH + sp ) >> 2];
            f10 = O4[(ob + CH + s10) >> 2];
            f01 = O4[(ob + CH + s01) >> 2];
            f11 = O4[(ob + CH + s11) >> 2];
        } else {
            f00 = f10 = f01 = f11 = make_float4(0.f, 0.f, 0.f, 0.f);
        }
        float Y00[5] = {f00.x, f00.y, f00.z, f00.w, __shfl_down_sync(FULL, f00.x, 1)};
        float Y10[5] = {f10.x, f10.y, f10.z, f10.w, __shfl_down_sync(FULL, f10.x, 1)};
        float Y01[5] = {f01.x, f01.y, f01.z, f01.w, __shfl_down_sync(FULL, f01.x, 1)};
        float Y11[5] = {f11.x, f11.y, f11.z, f11.w, __shfl_down_sync(FULL, f11.x, 1)};
        if (live) {
#pragma unroll
            for (int j = 0; j < 4; j++) {
                float dk00 = Z00[j+1] - Z00[j];
                float dk10 = Z10[j+1] - Z10[j];
                float dk01 = Z01[j+1] - Z01[j];
                float dk11 = Z11[j+1] - Z11[j];
                float py = 0.125f * ((Y01[j] + Y11[j] + Y01[j+1] + Y11[j+1]) * (dk01 + dk11)
                                   - (Y00[j] + Y10[j] + Y00[j+1] + Y10[j+1]) * (dk00 + dk10))
                         + SIXTH  * ((Y10[j+1] + Y11[j+1] + Y01[j+1]) * (Z10[j+1] - Z11[j+1])
                                   + (Y00[j+1] + Y01[j+1] + Y11[j+1]) * (Z00[j+1] - Z01[j+1])
                                   - (Y10[j] + Y11[j] + Y01[j]) * (Z10[j] - Z11[j])
                                   - (Y00[j] + Y01[j] + Y11[j]) * (Z00[j] - Z01[j]));
                float byc = 0.125f * (Y00[j] + Y10[j] + Y01[j] + Y11[j]
                                    + Y00[j+1] + Y10[j+1] + Y01[j+1] + Y11[j+1]);
                num[j] += DXf * py;
                den[j] += byc * byc;
            }
        }
    }

    // ---------- phase BZ + finalize cells ----------
    float accd = 0.f;
    {
        float4 f00, f10, f01, f11;
        if (live) {
            f00 = O4[(ob + 2*CH + sp ) >> 2];
            f10 = O4[(ob + 2*CH + s10) >> 2];
            f01 = O4[(ob + 2*CH + s01) >> 2];
            f11 = O4[(ob + 2*CH + s11) >> 2];
        } else {
            f00 = f10 = f01 = f11 = make_float4(0.f, 0.f, 0.f, 0.f);
        }
        float V00[5] = {f00.x, f00.y, f00.z, f00.w, __shfl_down_sync(FULL, f00.x, 1)};
        float V10[5] = {f10.x, f10.y, f10.z, f10.w, __shfl_down_sync(FULL, f10.x, 1)};
        float V01[5] = {f01.x, f01.y, f01.z, f01.w, __shfl_down_sync(FULL, f01.x, 1)};
        float V11[5] = {f11.x, f11.y, f11.z, f11.w, __shfl_down_sync(FULL, f11.x, 1)};
        if (live) {
#pragma unroll
            for (int j = 0; j < 4; j++) {
                if (j < 3 || tx < 15) {       // cell k = 4*tx + j < 63
                    float szLo = V00[j]   + V01[j]   + V10[j]   + V11[j];
                    float szHi = V00[j+1] + V01[j+1] + V10[j+1] + V11[j+1];
                    float n = num[j] + (DXf * DYf) * (0.25f * (szHi - szLo));
                    float bzc = 0.125f * (szHi + szLo);
                    float d = den[j] + bzc * bzc + EPSF;
                    accd += __fdividef(n * n, d);
                }
            }
        }
    }

    // ---- reduction -> atomic -> last-block finalize ----
    double dd = (double)accd;
#pragma unroll
    for (int o = 16; o > 0; o >>= 1)
        dd += __shfl_xor_sync(FULL, dd, o);
    __shared__ double sd[4];
    const int lin = ty * 16 + tx;
    if ((lin & 31) == 0) sd[lin >> 5] = dd;
    __syncthreads();
    if (lin == 0) {
        atomicAdd(&g_acc[2], sd[0] + sd[1] + sd[2] + sd[3]);
        __threadfence();
        unsigned int prev = atomicAdd(&g_done, 1u);
        if (prev == (unsigned)(nblocks - 1)) {
            __threadfence();
            const double N1 = 8388608.0;   // 2*256*256*64
            const double N2 = 8193150.0;   // 2*255*255*63
            double lb = g_acc[0] / N1;
            double lp = g_acc[1] / N1;
            double ld = g_acc[2] / N2;
            double dx2 = 0.1 * 0.1;
            out[0] = (float)(1000.0 * lb + 1000.0 * lp);
            out[1] = (float)(100.0 * ld / dx2 / dx2);
            g_acc[0] = 0.0; g_acc[1] = 0.0; g_acc[2] = 0.0;
            g_done = 0u;
            __threadfence();
        }
    }
}

extern "C" void kernel_launch(void* const* d_in, const int* in_sizes, int n_in,
                              void* d_out, int out_size) {
    const float* O = (const float*)d_in[0];   // outputs (2,3,256,256,64)
    const float* T = (const float*)d_in[1];   // targets (2,4,256,256,64)
    k_pw<<<4096, 256>>>(O, T);                         // 2*CH/8 threads
    k_div<<<16384, dim3(16, 8)>>>(O, T, (float*)d_out, 16384);
}

// round 16
// speedup vs baseline: 1.4766x; 1.0356x over previous
#include <cuda_runtime.h>

#define CH   4194304      // 256*256*64 = 2^22
#define SXY  16384        // 256*64 (x stride)
#define EPSF 1e-10f

__device__ double g_acc[3];        // [0]=loss_b, [1]=parallel, [2]=div
__device__ unsigned int g_done;    // zero-initialized

// ============================================================================
// Kernel A: pointwise losses. 16 floats/thread/channel-group -> 24 LDG.128
// in flight per thread. Pure stream.
// ============================================================================
__global__ __launch_bounds__(256)
void k_pw(const float* __restrict__ O, const float* __restrict__ T) {
    const int t   = blockIdx.x * 256 + threadIdx.x;   // 0 .. 2*CH/16 - 1
    const int off = t << 4;                           // element offset, 16/thread
    const int b   = off >> 22;                        // batch
    const int sp  = off & (CH - 1);                   // 16-aligned, same channel
    const int ob  = b * 3 * CH;
    const int tb  = b * 4 * CH;
    const float4* O4 = (const float4*)O;
    const float4* T4 = (const float4*)T;

    const int i0 = (ob          + sp) >> 2;
    const int i1 = (ob + CH     + sp) >> 2;
    const int i2 = (ob + 2*CH   + sp) >> 2;
    const int j0 = (tb          + sp) >> 2;
    const int j1 = (tb + CH     + sp) >> 2;
    const int j2 = (tb + 2*CH   + sp) >> 2;

    float accb = 0.f, accp = 0.f;

#define PW(px, py, pz, qx, qy, qz) {                                   \
    float qx2 = (qx)*(qx), qy2 = (qy)*(qy), qz2 = (qz)*(qz);           \
    float v1 = (px)*(px) + (py)*(py) - qx2 - qy2;                      \
    accb += __fdividef(v1 * v1, qx2 + qy2 + EPSF);                     \
    float dz = (pz) - (qz); float dz2 = dz * dz;                       \
    accb += __fdividef(dz2 * dz2, qz2 + EPSF);                         \
    float cr = (px)*(qy) - (py)*(qx);                                  \
    accp += __fdividef(cr * cr, qx2 + qy2 + qz2 + EPSF); }

#pragma unroll
    for (int u = 0; u < 4; u++) {
        float4 pbx = O4[i0 + u];
        float4 pby = O4[i1 + u];
        float4 pbz = O4[i2 + u];
        float4 qbx = T4[j0 + u];
        float4 qby = T4[j1 + u];
        float4 qbz = T4[j2 + u];
        PW(pbx.x, pby.x, pbz.x, qbx.x, qby.x, qbz.x);
        PW(pbx.y, pby.y, pbz.y, qbx.y, qby.y, qbz.y);
        PW(pbx.z, pby.z, pbz.z, qbx.z, qby.z, qbz.z);
        PW(pbx.w, pby.w, pbz.w, qbx.w, qby.w, qbz.w);
    }
#undef PW

    double db = (double)accb, dp = (double)accp;
#pragma unroll
    for (int o = 16; o > 0; o >>= 1) {
        db += __shfl_xor_sync(0xffffffffu, db, o);
        dp += __shfl_xor_sync(0xffffffffu, dp, o);
    }
    __shared__ double sb[8], sp_[8];
    const int lin = threadIdx.x;
    if ((lin & 31) == 0) { sb[lin >> 5] = db; sp_[lin >> 5] = dp; }
    __syncthreads();
    if (lin == 0) {
        double a = 0.0, c = 0.0;
#pragma unroll
        for (int w = 0; w < 8; w++) { a += sb[w]; c += sp_[w]; }
        atomicAdd(&g_acc[0], a);
        atomicAdd(&g_acc[1], c);
    }
}

// ============================================================================
// Kernel B: divergence loss — R10 version (front-batched 16 LDG.128, direct
// component consumption, shfl tails for the j=3 cell). Measured 69.2 us.
// ============================================================================
__device__ __forceinline__ float cell_div(
    float bx000, float bx100, float bx010, float bx110,
    float bx001, float bx101, float bx011, float bx111,
    float by000, float by100, float by010, float by110,
    float by001, float by101, float by011, float by111,
    float bz000, float bz100, float bz010, float bz110,
    float bz001, float bz101, float bz011, float bz111,
    float z000,  float z100,  float z010,  float z110,
    float z001,  float z101,  float z011,  float z111)
{
    const float DXf = 0.1f, DYf = 0.1f, SIXTH = 1.f / 6.f;
    float dk00 = z001 - z000;
    float dk10 = z101 - z100;
    float dk01 = z011 - z010;
    float dk11 = z111 - z110;

    float px = 0.125f * ((bx100 + bx110 + bx101 + bx111) * (dk10 + dk11)
                       - (bx000 + bx010 + bx001 + bx011) * (dk00 + dk01))
             + SIXTH  * ((bx001 + bx101 + bx111) * (z001 - z101)
                       + (bx011 + bx111 + bx101) * (z011 - z111)
                       - (bx000 + bx100 + bx110) * (z000 - z100)
                       - (bx010 + bx110 + bx100) * (z010 - z110));

    float py = 0.125f * ((by010 + by110 + by011 + by111) * (dk01 + dk11)
                       - (by000 + by100 + by001 + by101) * (dk00 + dk10))
             + SIXTH  * ((by101 + by111 + by011) * (z101 - z111)
                       + (by001 + by011 + by111) * (z001 - z011)
                       - (by100 + by110 + by010) * (z100 - z110)
                       - (by000 + by010 + by110) * (z000 - z010));

    float szHi = bz001 + bz011 + bz101 + bz111;
    float szLo = bz000 + bz010 + bz100 + bz110;
    float pz = 0.25f * (szHi - szLo);

    float num = DYf * px + DXf * py + (DXf * DYf) * pz;

    float bxc = 0.125f * (bx000 + bx100 + bx010 + bx110 + bx001 + bx101 + bx011 + bx111);
    float byc = 0.125f * (by000 + by100 + by010 + by110 + by001 + by101 + by011 + by111);
    float bzc = 0.125f * (szHi + szLo);
    float den = bxc*bxc + byc*byc + bzc*bzc + EPSF;
    return __fdividef(num * num, den);
}

// tx 0..15 -> k0=4*tx, ty 0..7 -> y in group. Grid 16384 = b(2)*x(256)*yg(32).
__global__ __launch_bounds__(128, 6)
void k_div(const float* __restrict__ O, const float* __restrict__ T,
           float* __restrict__ out, int nblocks) {
    const int tx = threadIdx.x;
    const int ty = threadIdx.y;
    const int bid = blockIdx.x;
    const int y  = ((bid & 31) << 3) + ty;
    const int x  = (bid >> 5) & 255;
    const int b  = bid >> 13;
    const int sp = (x * 256 + y) * 64 + (tx << 2);
    const int ob = b * 3 * CH;
    const int cz = b * 4 * CH + 3 * CH;   // targets channel 3

    const float4* O4 = (const float4*)O;
    const float4* T4 = (const float4*)T;
    const bool live = (x < 255) && (y < 255);

    float4 ax00, ax10, ax01, ax11;   // bx at (0,0),(1,0),(0,1),(1,1)
    float4 ay00, ay10, ay01, ay11;   // by
    float4 az00, az10, az01, az11;   // bz
    float4 aw00, aw10, aw01, aw11;   // z (targets ch3)
    if (live) {
        const int s10 = sp + SXY;
        const int s01 = sp + 64;
        const int s11 = s10 + 64;
        ax00 = O4[(ob          + sp ) >> 2];
        ax10 = O4[(ob          + s10) >> 2];
        ax01 = O4[(ob          + s01) >> 2];
        ax11 = O4[(ob          + s11) >> 2];
        ay00 = O4[(ob + CH     + sp ) >> 2];
        ay10 = O4[(ob + CH     + s10) >> 2];
        ay01 = O4[(ob + CH     + s01) >> 2];
        ay11 = O4[(ob + CH     + s11) >> 2];
        az00 = O4[(ob + 2*CH   + sp ) >> 2];
        az10 = O4[(ob + 2*CH   + s10) >> 2];
        az01 = O4[(ob + 2*CH   + s01) >> 2];
        az11 = O4[(ob + 2*CH   + s11) >> 2];
        aw00 = T4[(cz          + sp ) >> 2];
        aw10 = T4[(cz          + s10) >> 2];
        aw01 = T4[(cz          + s01) >> 2];
        aw11 = T4[(cz          + s11) >> 2];
    } else {
        ax00 = ax10 = ax01 = ax11 = ay00 = ay10 = ay01 = ay11 =
        az00 = az10 = az01 = az11 = aw00 = aw10 = aw01 = aw11 =
            make_float4(0.f, 0.f, 0.f, 0.f);
    }

    // k0+4 tails from lane+1's .x (warp lane = (ty&1)*16+tx; lane 15/31
    // results are unused: tx==15 has no j==3 cell).
    const unsigned FULL = 0xffffffffu;
    float tx00 = __shfl_down_sync(FULL, ax00.x, 1);
    float tx10 = __shfl_down_sync(FULL, ax10.x, 1);
    float tx01 = __shfl_down_sync(FULL, ax01.x, 1);
    float tx11 = __shfl_down_sync(FULL, ax11.x, 1);
    float ty00 = __shfl_down_sync(FULL, ay00.x, 1);
    float ty10 = __shfl_down_sync(FULL, ay10.x, 1);
    float ty01 = __shfl_down_sync(FULL, ay01.x, 1);
    float ty11 = __shfl_down_sync(FULL, ay11.x, 1);
    float tz00 = __shfl_down_sync(FULL, az00.x, 1);
    float tz10 = __shfl_down_sync(FULL, az10.x, 1);
    float tz01 = __shfl_down_sync(FULL, az01.x, 1);
    float tz11 = __shfl_down_sync(FULL, az11.x, 1);
    float tw00 = __shfl_down_sync(FULL, aw00.x, 1);
    float tw10 = __shfl_down_sync(FULL, aw10.x, 1);
    float tw01 = __shfl_down_sync(FULL, aw01.x, 1);
    float tw11 = __shfl_down_sync(FULL, aw11.x, 1);

    float accd = 0.f;
    if (live) {
        accd += cell_div(ax00.x, ax10.x, ax01.x, ax11.x,  ax00.y, ax10.y, ax01.y, ax11.y,
                         ay00.x, ay10.x, ay01.x, ay11.x,  ay00.y, ay10.y, ay01.y, ay11.y,
                         az00.x, az10.x, az01.x, az11.x,  az00.y, az10.y, az01.y, az11.y,
                         aw00.x, aw10.x, aw01.x, aw11.x,  aw00.y, aw10.y, aw01.y, aw11.y);
        accd += cell_div(ax00.y, ax10.y, ax01.y, ax11.y,  ax00.z, ax10.z, ax01.z, ax11.z,
                         ay00.y, ay10.y, ay01.y, ay11.y,  ay00.z, ay10.z, ay01.z, ay11.z,
                         az00.y, az10.y, az01.y, az11.y,  az00.z, az10.z, az01.z, az11.z,
                         aw00.y, aw10.y, aw01.y, aw11.y,  aw00.z, aw10.z, aw01.z, aw11.z);
        accd += cell_div(ax00.z, ax10.z, ax01.z, ax11.z,  ax00.w, ax10.w, ax01.w, ax11.w,
                         ay00.z, ay10.z, ay01.z, ay11.z,  ay00.w, ay10.w, ay01.w, ay11.w,
                         az00.z, az10.z, az01.z, az11.z,  az00.w, az10.w, az01.w, az11.w,
                         aw00.z, aw10.z, aw01.z, aw11.z,  aw00.w, aw10.w, aw01.w, aw11.w);
        if (tx < 15) {
            accd += cell_div(ax00.w, ax10.w, ax01.w, ax11.w,  tx00, tx10, tx01, tx11,
                             ay00.w, ay10.w, ay01.w, ay11.w,  ty00, ty10, ty01, ty11,
                             az00.w, az10.w, az01.w, az11.w,  tz00, tz10, tz01, tz11,
                             aw00.w, aw10.w, aw01.w, aw11.w,  tw00, tw10, tw01, tw11);
        }
    }

    // ---- reduction -> atomic -> last-block finalize ----
    double dd = (double)accd;
#pragma unroll
    for (int o = 16; o > 0; o >>= 1)
        dd += __shfl_xor_sync(FULL, dd, o);
    __shared__ double sd[4];
    const int lin = ty * 16 + tx;
    if ((lin & 31) == 0) sd[lin >> 5] = dd;
    __syncthreads();
    if (lin == 0) {
        atomicAdd(&g_acc[2], sd[0] + sd[1] + sd[2] + sd[3]);
        __threadfence();
        unsigned int prev = atomicAdd(&g_done, 1u);
        if (prev == (unsigned)(nblocks - 1)) {
            __threadfence();
            const double N1 = 8388608.0;   // 2*256*256*64
            const double N2 = 8193150.0;   // 2*255*255*63
            double lb = g_acc[0] / N1;
            double lp = g_acc[1] / N1;
            double ld = g_acc[2] / N2;
            double dx2 = 0.1 * 0.1;
            out[0] = (float)(1000.0 * lb + 1000.0 * lp);
            out[1] = (float)(100.0 * ld / dx2 / dx2);
            g_acc[0] = 0.0; g_acc[1] = 0.0; g_acc[2] = 0.0;
            g_done = 0u;
            __threadfence();
        }
    }
}

extern "C" void kernel_launch(void* const* d_in, const int* in_sizes, int n_in,
                              void* d_out, int out_size) {
    const float* O = (const float*)d_in[0];   // outputs (2,3,256,256,64)
    const float* T = (const float*)d_in[1];   // targets (2,4,256,256,64)
    k_pw<<<2048, 256>>>(O, T);                         // 2*CH/16 threads
    k_div<<<16384, dim3(16, 8)>>>(O, T, (float*)d_out, 16384);
}